// round 15
// baseline (speedup 1.0000x reference)
#include <cuda_runtime.h>
#include <math.h>

#define BB 8
#define NN 8192
#define SS 2048
#define KK 32
#define RAD 0.2f
#define EPSV 1e-5f

// NO __device__ globals, NO scratch. Intermediate state lives in d_out:
//   out[0 .. B*S*3)  = new_xyz (fps)
//   out[B*S*3 ..]    = out_feat rows; bq stashes 32 neighbor ints at each row
//                      head, mlp reads then overwrites.

// ---------------- packed f32x2 helpers (per-half IEEE fp32 rn — proven bit-exact R9) ----
__device__ __forceinline__ unsigned long long pack2(float x) {
    unsigned long long r;
    asm("mov.b64 %0, {%1, %1};" : "=l"(r) : "f"(x));
    return r;
}
__device__ __forceinline__ unsigned long long pack2v(float lo, float hi) {
    unsigned long long r;
    asm("mov.b64 %0, {%1, %2};" : "=l"(r) : "f"(lo), "f"(hi));
    return r;
}
__device__ __forceinline__ void add2(unsigned long long& o, unsigned long long a, unsigned long long b) {
    asm("add.rn.f32x2 %0, %1, %2;" : "=l"(o) : "l"(a), "l"(b));
}
__device__ __forceinline__ void mul2(unsigned long long& o, unsigned long long a, unsigned long long b) {
    asm("mul.rn.f32x2 %0, %1, %2;" : "=l"(o) : "l"(a), "l"(b));
}
__device__ __forceinline__ void ffma2(unsigned long long& a, unsigned long long w, unsigned long long x) {
    asm("fma.rn.f32x2 %0, %1, %2, %0;" : "+l"(a) : "l"(w), "l"(x));
}
__device__ __forceinline__ float2 unpack2(unsigned long long a) {
    float2 f;
    asm("mov.b64 {%0, %1}, %2;" : "=f"(f.x), "=f"(f.y) : "l"(a));
    return f;
}

// ---------------- farthest point sampling ----------------
// Value-first reduction. Thread max via pure fmaxf tree (15 ops, no index).
// Block max via REDUX + one barrier. Index recovered ONLY by the (typically 1)
// warp holding the block max: descending-j scan => lowest global index among
// exact-bit maximizers == first occurrence. Second barrier shares the winner.
// Distance math (packed add/mul, reference op order) unchanged.
#define FPS_T 512
#define FPS_SMEM_BYTES (3 * NN * (int)sizeof(float))
__global__ void __launch_bounds__(FPS_T) fps_kernel(const float* __restrict__ xyz,
                                                    float* __restrict__ out_xyz)
{
    extern __shared__ float fsm[];
    float* sx = fsm;
    float* sy = fsm + NN;
    float* sz = fsm + 2 * NN;
    __shared__ unsigned s_vb[2][16];
    __shared__ unsigned s_wi[2][16];

    const int b = blockIdx.x, tid = threadIdx.x;
    const float* X = xyz + (size_t)b * NN * 3;

    unsigned long long px2[8], py2[8], pz2[8];
    float mind[16];
#pragma unroll
    for (int k = 0; k < 8; k++) {
        int ilo = (2 * k) * FPS_T + tid, ihi = ilo + FPS_T;
        float xl = X[3 * ilo], yl = X[3 * ilo + 1], zl = X[3 * ilo + 2];
        float xh = X[3 * ihi], yh = X[3 * ihi + 1], zh = X[3 * ihi + 2];
        px2[k] = pack2v(xl, xh); py2[k] = pack2v(yl, yh); pz2[k] = pack2v(zl, zh);
        sx[ilo] = xl; sy[ilo] = yl; sz[ilo] = zl;
        sx[ihi] = xh; sy[ihi] = yh; sz[ihi] = zh;
        mind[2 * k] = 1e10f; mind[2 * k + 1] = 1e10f;
    }
    if (tid == 0) {
        float* o = out_xyz + (size_t)b * SS * 3;
        o[0] = X[0]; o[1] = X[1]; o[2] = X[2];   // sample 0 = index 0
    }
    __syncthreads();

    const int lane = tid & 31, warp = tid >> 5;  // 16 warps
    int w = 0;
    for (int s = 1; s < SS; s++) {
        const int par = s & 1;
        const unsigned long long nlx = pack2(-sx[w]);
        const unsigned long long nly = pack2(-sy[w]);
        const unsigned long long nlz = pack2(-sz[w]);
#pragma unroll
        for (int k = 0; k < 8; k++) {
            unsigned long long dx, dy, dz, xx, yy, zz, s12, dd;
            add2(dx, px2[k], nlx);
            add2(dy, py2[k], nly);
            add2(dz, pz2[k], nlz);
            mul2(xx, dx, dx);
            mul2(yy, dy, dy);
            mul2(zz, dz, dz);
            add2(s12, xx, yy);
            add2(dd, s12, zz);
            float2 d = unpack2(dd);
            mind[2 * k]     = fminf(mind[2 * k], d.x);
            mind[2 * k + 1] = fminf(mind[2 * k + 1], d.y);
        }
        // thread max: pure value tree (no index tracking)
        float m8[8];
#pragma unroll
        for (int n = 0; n < 8; n++) m8[n] = fmaxf(mind[2 * n], mind[2 * n + 1]);
        float m4a = fmaxf(m8[0], m8[1]), m4b = fmaxf(m8[2], m8[3]);
        float m4c = fmaxf(m8[4], m8[5]), m4d = fmaxf(m8[6], m8[7]);
        float m2a = fmaxf(m4a, m4b), m2b = fmaxf(m4c, m4d);
        float tm = fmaxf(m2a, m2b);

        unsigned tb = __float_as_uint(tm);               // dist >= 0 -> bits monotone
        unsigned wmax = __reduce_max_sync(0xffffffffu, tb);
        if (lane == 0) s_vb[par][warp] = wmax;
        __syncthreads();
        unsigned v = (lane < 16) ? s_vb[par][lane] : 0u;
        unsigned bmax = __reduce_max_sync(0xffffffffu, v);

        // index recovery: only lanes holding the block max scan their 16 minds
        unsigned cand = 0xffffffffu;
        if (tb == bmax) {
#pragma unroll
            for (int j = 15; j >= 0; j--)
                if (__float_as_uint(mind[j]) == bmax) cand = (unsigned)(j * FPS_T + tid);
        }
        unsigned wmin = __reduce_min_sync(0xffffffffu, cand);
        if (lane == 0) s_wi[par][warp] = wmin;
        __syncthreads();
        unsigned ii = (lane < 16) ? s_wi[par][lane] : 0xffffffffu;
        w = (int)__reduce_min_sync(0xffffffffu, ii);

        if (tid == 0) {
            float* o = out_xyz + ((size_t)b * SS + s) * 3;
            o[0] = sx[w]; o[1] = sy[w]; o[2] = sz[w];
        }
    }
}

// ---------------- ball query (unchanged R13): warp-per-query register top-32 ----------------
#define BQ2_T 256
__global__ void __launch_bounds__(BQ2_T) bq_kernel(const float* __restrict__ xyz,
                                                   const float* __restrict__ newxyz,
                                                   float* __restrict__ out_feat)
{
    const int t = threadIdx.x, lane = t & 31, warp = t >> 5;
    const int q = blockIdx.x * 8 + warp;          // 0 .. B*S-1
    const int b = q >> 11;
    const float* X = xyz + (size_t)b * NN * 3;

    const float qx = newxyz[(size_t)q * 3 + 0];
    const float qy = newxyz[(size_t)q * 3 + 1];
    const float qz = newxyz[(size_t)q * 3 + 2];
    const float a2 = __fadd_rn(__fadd_rn(__fmul_rn(qx, qx), __fmul_rn(qy, qy)), __fmul_rn(qz, qz));

    float myk = 3.4e38f;          // lane j = j-th smallest key
    int   myi = 0x7fffffff;
    float worst = 3.4e38f;        // == lane 31's key, kept warp-uniform

#pragma unroll 1
    for (int c0 = 0; c0 < NN; c0 += 32) {
        const int ci = c0 + lane;
        const float x = X[ci * 3 + 0];
        const float y = X[ci * 3 + 1];
        const float z = X[ci * 3 + 2];
        const float b2 = __fadd_rn(__fadd_rn(__fmul_rn(x, x), __fmul_rn(y, y)), __fmul_rn(z, z));
        const float ab = __fadd_rn(__fadd_rn(__fmul_rn(qx, x), __fmul_rn(qy, y)), __fmul_rn(qz, z));
        const float key = fmaxf(__fadd_rn(__fadd_rn(a2, b2), __fmul_rn(-2.0f, ab)), 0.0f);

        unsigned pass = __ballot_sync(0xffffffffu, key < worst);
        while (pass) {
            const int src = __ffs(pass) - 1;      // ascending lane = ascending index
            pass &= pass - 1;
            const float nk = __shfl_sync(0xffffffffu, key, src);
            if (nk < worst) {                     // worst may have tightened
                unsigned gt = __ballot_sync(0xffffffffu, myk > nk);
                float upk = __shfl_up_sync(0xffffffffu, myk, 1);
                int   upi = __shfl_up_sync(0xffffffffu, myi, 1);
                int pos = __ffs(gt) - 1;          // gt != 0 since lane31 (worst) > nk
                if (lane > pos)       { myk = upk; myi = upi; }
                else if (lane == pos) { myk = nk;  myi = c0 + src; }
                worst = __shfl_sync(0xffffffffu, myk, 31);
            }
        }
    }

    int* nbrow = (int*)(out_feat + (size_t)q * 128);
    float dist = __fsqrt_rn(myk);
    nbrow[lane] = (dist < RAD) ? myi : 0;         // -1 sentinel clamps to 0 anyway
}

// ---------------- fused MLP (unchanged R13): 256 threads, f32x2 FMA ----------------
#define MLP_T 256
#define MLP_G 8
#define MLP_SMEM_FLOATS (4288 + 4096 + 8192 + 256 + 256 + 16384 + 16384)
__global__ void __launch_bounds__(MLP_T) mlp_kernel(
    const float* __restrict__ xyz, const float* __restrict__ feat,
    const float* __restrict__ W0, const float* __restrict__ b0, const float* __restrict__ gg0,
    const float* __restrict__ be0, const float* __restrict__ m0, const float* __restrict__ v0,
    const float* __restrict__ W1, const float* __restrict__ b1, const float* __restrict__ gg1,
    const float* __restrict__ be1, const float* __restrict__ m1, const float* __restrict__ v1,
    const float* __restrict__ W2, const float* __restrict__ b2, const float* __restrict__ gg2,
    const float* __restrict__ be2, const float* __restrict__ m2, const float* __restrict__ v2,
    const float* __restrict__ newxyz, float* __restrict__ out_feat)
{
    extern __shared__ float dsm[];
    float* sW0T = dsm;                 // 4288  [c<67][o<64] folded
    float* sW1T = sW0T + 4288;         // 4096  [c][o]
    float* sW2T = sW1T + 4096;         // 8192  [c][o<128]
    float* sC   = sW2T + 8192;         // 256: C0[64] C1[64] C2[128]
    float* sS   = sC + 256;            // 256: s0[64] s1[64] s2[128]
    float* sF   = sS + 256;            // 16384 [c][t] feats, later h1
    float* sH   = sF + 16384;          // 16384 [c][t] h0

    const int t = threadIdx.x;
    if (t < 64) {
        float s0 = gg0[t] / sqrtf(v0[t] + EPSV);
        float s1 = gg1[t] / sqrtf(v1[t] + EPSV);
        sS[t] = s0; sS[64 + t] = s1;
        sC[t] = (b0[t] - m0[t]) * s0 + be0[t];
        sC[64 + t] = (b1[t] - m1[t]) * s1 + be1[t];
    }
    if (t < 128) {
        float s2 = gg2[t] / sqrtf(v2[t] + EPSV);
        sS[128 + t] = s2;
        sC[128 + t] = (b2[t] - m2[t]) * s2 + be2[t];
    }
    __syncthreads();
    for (int i = t; i < 67 * 64; i += MLP_T)  { int c = i >> 6, o = i & 63;  sW0T[i] = W0[o * 67 + c] * sS[o]; }
    for (int i = t; i < 64 * 64; i += MLP_T)  { int c = i >> 6, o = i & 63;  sW1T[i] = W1[o * 64 + c] * sS[64 + o]; }
    for (int i = t; i < 64 * 128; i += MLP_T) { int c = i >> 7, o = i & 127; sW2T[i] = W2[o * 64 + c] * sS[128 + o]; }
    __syncthreads();

    const int warp = t >> 5, lane = t & 31;   // 8 warps = 8 queries per pass

#pragma unroll 1
    for (int g = 0; g < MLP_G; g++) {
        const int q = (blockIdx.x * MLP_G + g) * 8 + warp;
        const int b = q >> 11;
        const float nx = newxyz[(size_t)q * 3], ny = newxyz[(size_t)q * 3 + 1], nz = newxyz[(size_t)q * 3 + 2];
        float* orow = out_feat + (size_t)q * 128;

        const int nbi = ((const int*)orow)[lane];     // read before any row write
        const float* prow = xyz + ((size_t)b * NN + nbi) * 3;
        const float dx = prow[0] - nx, dy = prow[1] - ny, dz = prow[2] - nz;
        const unsigned long long dx2 = pack2(dx), dy2 = pack2(dy), dz2 = pack2(dz);
        const float* frow = feat + ((size_t)b * NN + nbi) * 64;
#pragma unroll
        for (int c = 0; c < 64; c += 4) {
            float4 v = *(const float4*)(frow + c);
            sF[(c + 0) * MLP_T + t] = v.x;
            sF[(c + 1) * MLP_T + t] = v.y;
            sF[(c + 2) * MLP_T + t] = v.z;
            sF[(c + 3) * MLP_T + t] = v.w;
        }

        // ---- layer 0: 67 -> 64, two halves of 32 outputs ----
#pragma unroll 1
        for (int half = 0; half < 2; half++) {
            unsigned long long acc2[16];
            const unsigned long long* cc = (const unsigned long long*)(sC + half * 32);
#pragma unroll
            for (int i = 0; i < 16; i++) acc2[i] = cc[i];
            {
                const ulonglong2* wr = (const ulonglong2*)(sW0T + 0 * 64 + half * 32);
#pragma unroll
                for (int i = 0; i < 8; i++) { ulonglong2 w = wr[i]; ffma2(acc2[2*i], w.x, dx2); ffma2(acc2[2*i+1], w.y, dx2); }
            }
            {
                const ulonglong2* wr = (const ulonglong2*)(sW0T + 1 * 64 + half * 32);
#pragma unroll
                for (int i = 0; i < 8; i++) { ulonglong2 w = wr[i]; ffma2(acc2[2*i], w.x, dy2); ffma2(acc2[2*i+1], w.y, dy2); }
            }
            {
                const ulonglong2* wr = (const ulonglong2*)(sW0T + 2 * 64 + half * 32);
#pragma unroll
                for (int i = 0; i < 8; i++) { ulonglong2 w = wr[i]; ffma2(acc2[2*i], w.x, dz2); ffma2(acc2[2*i+1], w.y, dz2); }
            }
#pragma unroll 2
            for (int c = 0; c < 64; c++) {
                unsigned long long x2 = pack2(sF[c * MLP_T + t]);
                const ulonglong2* wr = (const ulonglong2*)(sW0T + (3 + c) * 64 + half * 32);
#pragma unroll
                for (int i = 0; i < 8; i++) { ulonglong2 w = wr[i]; ffma2(acc2[2*i], w.x, x2); ffma2(acc2[2*i+1], w.y, x2); }
            }
#pragma unroll
            for (int i = 0; i < 16; i++) {
                float2 v = unpack2(acc2[i]);
                sH[(half * 32 + 2 * i + 0) * MLP_T + t] = fmaxf(v.x, 0.f);
                sH[(half * 32 + 2 * i + 1) * MLP_T + t] = fmaxf(v.y, 0.f);
            }
        }

        // ---- layer 1: 64 -> 64, two halves; h1 overwrites sF ----
#pragma unroll 1
        for (int half = 0; half < 2; half++) {
            unsigned long long acc2[16];
            const unsigned long long* cc = (const unsigned long long*)(sC + 64 + half * 32);
#pragma unroll
            for (int i = 0; i < 16; i++) acc2[i] = cc[i];
#pragma unroll 2
            for (int c = 0; c < 64; c++) {
                unsigned long long x2 = pack2(sH[c * MLP_T + t]);
                const ulonglong2* wr = (const ulonglong2*)(sW1T + c * 64 + half * 32);
#pragma unroll
                for (int i = 0; i < 8; i++) { ulonglong2 w = wr[i]; ffma2(acc2[2*i], w.x, x2); ffma2(acc2[2*i+1], w.y, x2); }
            }
#pragma unroll
            for (int i = 0; i < 16; i++) {
                float2 v = unpack2(acc2[i]);
                sF[(half * 32 + 2 * i + 0) * MLP_T + t] = fmaxf(v.x, 0.f);
                sF[(half * 32 + 2 * i + 1) * MLP_T + t] = fmaxf(v.y, 0.f);
            }
        }

        // ---- layer 2: 64 -> 128, four quarters; relu + warp-max + lane0 store ----
#pragma unroll 1
        for (int quar = 0; quar < 4; quar++) {
            unsigned long long acc2[16];
            const unsigned long long* cc = (const unsigned long long*)(sC + 128 + quar * 32);
#pragma unroll
            for (int i = 0; i < 16; i++) acc2[i] = cc[i];
#pragma unroll 2
            for (int c = 0; c < 64; c++) {
                unsigned long long x2 = pack2(sF[c * MLP_T + t]);
                const ulonglong2* wr = (const ulonglong2*)(sW2T + c * 128 + quar * 32);
#pragma unroll
                for (int i = 0; i < 8; i++) { ulonglong2 w = wr[i]; ffma2(acc2[2*i], w.x, x2); ffma2(acc2[2*i+1], w.y, x2); }
            }
#pragma unroll
            for (int i = 0; i < 16; i += 2) {
                float2 va = unpack2(acc2[i]);
                float2 vb = unpack2(acc2[i + 1]);
                float a0 = fmaxf(va.x, 0.f), a1 = fmaxf(va.y, 0.f);
                float a2 = fmaxf(vb.x, 0.f), a3 = fmaxf(vb.y, 0.f);
#pragma unroll
                for (int off = 16; off > 0; off >>= 1) {
                    a0 = fmaxf(a0, __shfl_xor_sync(0xffffffffu, a0, off));
                    a1 = fmaxf(a1, __shfl_xor_sync(0xffffffffu, a1, off));
                    a2 = fmaxf(a2, __shfl_xor_sync(0xffffffffu, a2, off));
                    a3 = fmaxf(a3, __shfl_xor_sync(0xffffffffu, a3, off));
                }
                if (lane == 0) *(float4*)(orow + quar * 32 + 2 * i) = make_float4(a0, a1, a2, a3);
            }
        }
    }
}

// ---------------- launch ----------------
extern "C" void kernel_launch(void* const* d_in, const int* in_sizes, int n_in,
                              void* d_out, int out_size)
{
    const float* xyz  = (const float*)d_in[0];
    const float* feat = (const float*)d_in[1];
    const float* a[18];
    for (int i = 0; i < 18; i++) a[i] = (const float*)d_in[2 + i];

    float* out = (float*)d_out;
    float* out_xyz  = out;                        // (B,S,3)
    float* out_feat = out + (size_t)BB * SS * 3;  // (B,S,128)

    cudaFuncSetAttribute(fps_kernel, cudaFuncAttributeMaxDynamicSharedMemorySize, FPS_SMEM_BYTES);
    fps_kernel<<<BB, FPS_T, FPS_SMEM_BYTES>>>(xyz, out_xyz);

    bq_kernel<<<BB * SS / 8, BQ2_T>>>(xyz, out_xyz, out_feat);

    int mlp_smem = MLP_SMEM_FLOATS * (int)sizeof(float);
    cudaFuncSetAttribute(mlp_kernel, cudaFuncAttributeMaxDynamicSharedMemorySize, mlp_smem);
    mlp_kernel<<<BB * SS / (8 * MLP_G), MLP_T, mlp_smem>>>(
        xyz, feat,
        a[0], a[1], a[2], a[3], a[4], a[5],
        a[6], a[7], a[8], a[9], a[10], a[11],
        a[12], a[13], a[14], a[15], a[16], a[17],
        out_xyz, out_feat);
}